// round 1
// baseline (speedup 1.0000x reference)
#include <cuda_runtime.h>
#include <cstdint>

#define TLEN   8192
#define BATCH  128
#define NS     128
#define EMITN  64

// ---- packed f32x2 helpers (sm_103a) ----
__device__ __forceinline__ void fma2(unsigned long long& d, unsigned long long a, unsigned long long b) {
    asm("fma.rn.f32x2 %0, %1, %2, %0;" : "+l"(d) : "l"(a), "l"(b));
}
__device__ __forceinline__ void add2(unsigned long long& d, unsigned long long a) {
    asm("add.rn.f32x2 %0, %1, %0;" : "+l"(d) : "l"(a));
}
__device__ __forceinline__ unsigned long long padd(unsigned long long a, unsigned long long b) {
    unsigned long long d;
    asm("add.rn.f32x2 %0, %1, %2;" : "=l"(d) : "l"(a), "l"(b));
    return d;
}
__device__ __forceinline__ unsigned long long pk(float lo, float hi) {
    unsigned long long r;
    asm("mov.b64 %0, {%1, %2};" : "=l"(r) : "f"(lo), "f"(hi));
    return r;
}
__device__ __forceinline__ float hsum2(unsigned long long v) {
    float lo, hi;
    asm("mov.b64 {%0, %1}, %2;" : "=f"(lo), "=f"(hi) : "l"(v));
    return lo + hi;
}

__global__ __launch_bounds__(128, 1)
void hmm_forward_kernel(const float* __restrict__ inputs,
                        const float* __restrict__ Ivec,
                        const float* __restrict__ Amat,
                        const float* __restrict__ Bmat,
                        float* __restrict__ out)
{
    __shared__ float Bsh[EMITN * NS];                 // 32 KB
    __shared__ unsigned char obs_sm[TLEN];            // 8 KB
    __shared__ __align__(16) float ubuf[2][NS];       // double-buffered alpha (unnormalized)
    __shared__ __align__(16) float zpart[4];          // per-warp quarter sums of u_{t-1}
    __shared__ __align__(16) float zfin[4];

    const int tid = threadIdx.x;        // == state index s
    const int b   = blockIdx.x;         // batch
    const int w   = tid >> 5;
    const int lane = tid & 31;
    const int w8  = w * 8;              // warp-rotated chunk start

    // ---- prologue: B into smem ----
    for (int i = tid; i < EMITN * NS; i += 128) Bsh[i] = Bmat[i];

    // ---- prologue: one-hot -> obs index (exact, dot with iota) ----
    {
        const float* xin = inputs + (size_t)b * TLEN * EMITN;
        for (int t = tid; t < TLEN; t += 128) {
            const float4* r = (const float4*)(xin + (size_t)t * EMITN);
            float idx = 0.0f;
            #pragma unroll
            for (int j = 0; j < 16; j++) {
                float4 v = r[j];
                idx = fmaf((float)(4 * j + 0), v.x, idx);
                idx = fmaf((float)(4 * j + 1), v.y, idx);
                idx = fmaf((float)(4 * j + 2), v.z, idx);
                idx = fmaf((float)(4 * j + 3), v.w, idx);
            }
            obs_sm[t] = (unsigned char)__float2int_rn(idx);
        }
    }

    // ---- prologue: A column s into registers, warp-rotated chunk order ----
    // Chunk c covers k in [4c, 4c+4). Warp w iterates chunks (8w+j)&31 so that
    // its first 8 chunks are exactly states [32w, 32w+32) -> warp quarter sum of u.
    unsigned long long Ar[64];
    #pragma unroll
    for (int j = 0; j < 32; j++) {
        int c = (w8 + j) & 31;
        int k0 = 4 * c;
        float a0 = Amat[(k0 + 0) * NS + tid];
        float a1 = Amat[(k0 + 1) * NS + tid];
        float a2 = Amat[(k0 + 2) * NS + tid];
        float a3 = Amat[(k0 + 3) * NS + tid];
        Ar[2 * j]     = pk(a0, a1);
        Ar[2 * j + 1] = pk(a2, a3);
    }

    float Ival = Ivec[tid];
    __syncthreads();

    // ---- t = 0: u0 = E0 * I  (u_t == alpha_t exactly; scaling folded per step) ----
    int o0 = obs_sm[0];
    float u_new = Bsh[o0 * NS + tid] * Ival;
    ubuf[0][tid] = u_new;
    double ll = 0.0;
    __syncthreads();

    // ---- main recurrence ----
    for (int t = 1; t < TLEN; t++) {
        const ulonglong2* rp = (const ulonglong2*)ubuf[(t - 1) & 1];
        int o = obs_sm[t];
        float E = Bsh[o * NS + tid];

        unsigned long long acc0 = 0, acc1 = 0, acc2 = 0, acc3 = 0;
        unsigned long long za = 0, zb = 0;

        // first 8 chunks: matvec partial + this warp's quarter-sum of u_{t-1}
        #pragma unroll
        for (int j = 0; j < 8; j++) {
            ulonglong2 up = rp[(w8 + j) & 31];
            if (j & 1) { fma2(acc2, up.x, Ar[2 * j]); fma2(acc3, up.y, Ar[2 * j + 1]); }
            else       { fma2(acc0, up.x, Ar[2 * j]); fma2(acc1, up.y, Ar[2 * j + 1]); }
            add2(za, up.x);
            add2(zb, up.y);
        }
        if (lane == 0) zpart[w] = hsum2(padd(za, zb));
        __syncthreads();

        // Z combine hides under the remaining 24 chunks
        float4 zp = *(const float4*)zpart;
        float Z = (zp.x + zp.y) + (zp.z + zp.w);     // Z_{t-1} = sum(u_{t-1})
        float rZ = __frcp_rn(Z);
        float ErZ = E * rZ;
        ll += (double)__logf(Z);                      // log Z_{t-1}

        #pragma unroll
        for (int j = 8; j < 32; j++) {
            ulonglong2 up = rp[(w8 + j) & 31];
            if (j & 1) { fma2(acc2, up.x, Ar[2 * j]); fma2(acc3, up.y, Ar[2 * j + 1]); }
            else       { fma2(acc0, up.x, Ar[2 * j]); fma2(acc1, up.y, Ar[2 * j + 1]); }
        }

        float R = hsum2(padd(padd(acc0, acc1), padd(acc2, acc3)));
        u_new = ErZ * R;                              // alpha_t[s] exactly
        ubuf[t & 1][tid] = u_new;
        __syncthreads();
    }

    // ---- final Z for the last loglik term ----
    float v = u_new;
    #pragma unroll
    for (int off = 16; off > 0; off >>= 1) v += __shfl_xor_sync(0xffffffffu, v, off);
    if (lane == 0) zfin[w] = v;
    __syncthreads();

    out[b * NS + tid] = u_new;                        // alpha_f
    if (tid == 0) {
        float S = (zfin[0] + zfin[1]) + (zfin[2] + zfin[3]);
        ll += (double)__logf(S);
        out[BATCH * NS + b] = (float)ll;              // loglik
    }
}

extern "C" void kernel_launch(void* const* d_in, const int* in_sizes, int n_in,
                              void* d_out, int out_size)
{
    const float* inputs = (const float*)d_in[0];   // [128, 8192, 64]
    const float* Ivec   = (const float*)d_in[1];   // [128]
    const float* Amat   = (const float*)d_in[2];   // [128, 128]
    const float* Bmat   = (const float*)d_in[3];   // [64, 128]
    float* out = (float*)d_out;                    // alpha_f [128,128] ++ loglik [128]

    hmm_forward_kernel<<<BATCH, 128>>>(inputs, Ivec, Amat, Bmat, out);
}